// round 1
// baseline (speedup 1.0000x reference)
#include <cuda_runtime.h>

// GraphEmbedder: out[b,n,:] = pre[b,n,:] @ W + bias
// pre = sparse symmetric adjacency (last-write-wins scatter) + one-hot node block.
// Strategy: one CTA handles G_PER_CTA graphs; full W (192x256 f32 = 196KB) cached
// in SMEM; per-graph edge scatter into per-row SMEM lists with write-priority,
// dedupe by zeroing losing weights, then branch-free row-gather accumulate.

#define NUM_B   4096
#define NUM_E   256
#define NUM_N   128
#define NUM_F   64
#define PRE_DIM 192        // N + F
#define D_DIM   256
#define CAP     24         // max tracked writes per adjacency row (Poisson(4) tail ~1e-11)
#define G_PER_CTA 4
#define THREADS 256

// SMEM layout (bytes):
//   W:      PRE_DIM*D_DIM*4        = 196608
//   ent:    NUM_N*CAP*8            =  24576
//   counts: NUM_N*4                =    512
#define SMEM_W_FLOATS (PRE_DIM * D_DIM)
#define SMEM_BYTES (SMEM_W_FLOATS*4 + NUM_N*CAP*8 + NUM_N*4)

__global__ void __launch_bounds__(THREADS, 1)
graph_embed_kernel(const int*   __restrict__ edge_index,   // [B,E,2] int32
                   const float* __restrict__ edge_weight,  // [B,E]   f32
                   const int*   __restrict__ node_feat,    // [B,N]   int32
                   const float* __restrict__ Wg,           // [PRE,D] f32
                   const float* __restrict__ bias,         // [D]     f32
                   float*       __restrict__ out)          // [B,N,D] f32
{
    extern __shared__ unsigned char smem_raw[];
    float* Wsm = reinterpret_cast<float*>(smem_raw);
    unsigned long long* ent =
        reinterpret_cast<unsigned long long*>(smem_raw + SMEM_W_FLOATS * 4);
    int* counts = reinterpret_cast<int*>(ent + NUM_N * CAP);

    const int tid  = threadIdx.x;
    const int lane = tid & 31;
    const int wrp  = tid >> 5;
    const int dbase = lane * 8;     // each lane owns 8 consecutive d

    // ---- load W into SMEM (coalesced float4) ----
    {
        const float4* Wg4 = reinterpret_cast<const float4*>(Wg);
        float4* Ws4 = reinterpret_cast<float4*>(Wsm);
        #pragma unroll 4
        for (int i = tid; i < SMEM_W_FLOATS / 4; i += THREADS)
            Ws4[i] = Wg4[i];
    }

    // bias in registers (d-slice is fixed per lane)
    float bia[8];
    #pragma unroll
    for (int i = 0; i < 8; ++i) bia[i] = bias[dbase + i];

    for (int g = 0; g < G_PER_CTA; ++g) {
        const int b = blockIdx.x * G_PER_CTA + g;

        __syncthreads();                    // prev graph's compute done (ent/counts reuse)
        if (tid < NUM_N) counts[tid] = 0;
        __syncthreads();

        // ---- scatter: 1 thread = 1 edge (E == THREADS) ----
        {
            const int e = tid;
            const int2 ei = reinterpret_cast<const int2*>(edge_index)[(long long)b * NUM_E + e];
            const unsigned int wb =
                __float_as_uint(edge_weight[(long long)b * NUM_E + e]);
            const int i1 = ei.x, i2 = ei.y;
            // phase 1: out[i1][i2] = w   (priority = e)
            int p1 = atomicAdd(&counts[i1], 1);
            if (p1 < CAP)
                ent[i1 * CAP + p1] =
                    ((unsigned long long)e << 40) |
                    ((unsigned long long)(unsigned)i2 << 32) | wb;
            // phase 2: out[i2][i1] = w   (priority = 256 + e, beats all of phase 1)
            int p2 = atomicAdd(&counts[i2], 1);
            if (p2 < CAP)
                ent[i2 * CAP + p2] =
                    ((unsigned long long)(256 + e) << 40) |
                    ((unsigned long long)(unsigned)i1 << 32) | wb;
        }
        __syncthreads();

        // ---- dedupe: zero the weight of any entry beaten by a higher-priority
        //      write to the same (row, col). Keeps the hot loop branch-free. ----
        for (int s = tid; s < NUM_N * CAP; s += THREADS) {
            const int r = s / CAP, j = s - r * CAP;
            const int c = min(counts[r], CAP);
            if (j < c) {
                const unsigned long long ej = ent[s];
                const unsigned int keyj = (unsigned int)(ej >> 32); // prio<<8 | col
                const unsigned int colj = keyj & 0xFFu;
                bool dead = false;
                for (int k = 0; k < c; ++k) {
                    const unsigned int keyk = (unsigned int)(ent[r * CAP + k] >> 32);
                    if ((keyk & 0xFFu) == colj && keyk > keyj) dead = true;
                }
                if (dead) ent[s] = ej & ~0xFFFFFFFFull;  // weight := 0.0f
            }
        }
        __syncthreads();

        // ---- compute & store: warp `wrp` handles rows wrp, wrp+8, ... ----
        const int*  nfb  = node_feat + (long long)b * NUM_N;
        float*      outb = out + (long long)b * NUM_N * D_DIM;
        for (int r = wrp; r < NUM_N; r += 8) {
            const int nf = nfb[r];                         // broadcast load
            const float* Won = Wsm + (NUM_N + nf) * D_DIM + dbase;
            float acc[8];
            #pragma unroll
            for (int i = 0; i < 8; ++i) acc[i] = bia[i] + Won[i];

            const int c = min(counts[r], CAP);
            const unsigned long long* er = ent + r * CAP;
            for (int j = 0; j < c; ++j) {
                const unsigned long long ej = er[j];       // broadcast LDS
                const float w = __uint_as_float((unsigned int)ej);
                const float* Wr = Wsm + (int)((ej >> 32) & 0xFFu) * D_DIM + dbase;
                #pragma unroll
                for (int i = 0; i < 8; ++i) acc[i] = fmaf(w, Wr[i], acc[i]);
            }

            float4* o4 = reinterpret_cast<float4*>(outb + r * D_DIM + dbase);
            o4[0] = make_float4(acc[0], acc[1], acc[2], acc[3]);
            o4[1] = make_float4(acc[4], acc[5], acc[6], acc[7]);
        }
    }
}

extern "C" void kernel_launch(void* const* d_in, const int* in_sizes, int n_in,
                              void* d_out, int out_size)
{
    const int*   edge_index  = (const int*)  d_in[0];
    const float* edge_weight = (const float*)d_in[1];
    const int*   node_feat   = (const int*)  d_in[2];
    const float* W           = (const float*)d_in[3];
    const float* bias        = (const float*)d_in[4];
    float*       out         = (float*)      d_out;

    cudaFuncSetAttribute(graph_embed_kernel,
                         cudaFuncAttributeMaxDynamicSharedMemorySize, SMEM_BYTES);
    graph_embed_kernel<<<NUM_B / G_PER_CTA, THREADS, SMEM_BYTES>>>(
        edge_index, edge_weight, node_feat, W, bias, out);
}

// round 3
// speedup vs baseline: 1.2367x; 1.2367x over previous
#include <cuda_runtime.h>

// GraphEmbedder: out[b,n,:] = pre[b,n,:] @ W + bias
// pre = sparse symmetric adjacency (last-write-wins scatter) + one-hot node block.
// R2 (re-bench; prior attempt hit broker timeout): 768 threads (24 warps, was 8)
// to hide LDS latency; warp-per-row compute with warp-cooperative entry fetch +
// shuffle broadcast (kills the chained-LDS serial dependency that bound R1 at
// issue=20%, occ=12.5%).

#define NUM_B   4096
#define NUM_E   256
#define NUM_N   128
#define NUM_F   64
#define PRE_DIM 192        // N + F
#define D_DIM   256
#define CAP     24         // max tracked writes per adjacency row (Poisson(4) tail ~1e-12)
#define G_PER_CTA 4
#define THREADS 768
#define WARPS   (THREADS/32)

// SMEM: W 196608 B + ent 24576 B + counts 512 B = 221696 B
#define SMEM_W_FLOATS (PRE_DIM * D_DIM)
#define SMEM_BYTES (SMEM_W_FLOATS*4 + NUM_N*CAP*8 + NUM_N*4)

__global__ void __launch_bounds__(THREADS, 1)
graph_embed_kernel(const int*   __restrict__ edge_index,   // [B,E,2] int32
                   const float* __restrict__ edge_weight,  // [B,E]   f32
                   const int*   __restrict__ node_feat,    // [B,N]   int32
                   const float* __restrict__ Wg,           // [PRE,D] f32
                   const float* __restrict__ bias,         // [D]     f32
                   float*       __restrict__ out)          // [B,N,D] f32
{
    extern __shared__ unsigned char smem_raw[];
    float* Wsm = reinterpret_cast<float*>(smem_raw);
    unsigned long long* ent =
        reinterpret_cast<unsigned long long*>(smem_raw + SMEM_W_FLOATS * 4);
    int* counts = reinterpret_cast<int*>(ent + NUM_N * CAP);

    const int tid  = threadIdx.x;
    const int lane = tid & 31;
    const int wrp  = tid >> 5;
    const int dbase = lane * 8;     // each lane owns 8 consecutive d of the 256-wide row

    // ---- load W into SMEM (coalesced float4) ----
    {
        const float4* Wg4 = reinterpret_cast<const float4*>(Wg);
        float4* Ws4 = reinterpret_cast<float4*>(Wsm);
        #pragma unroll 2
        for (int i = tid; i < SMEM_W_FLOATS / 4; i += THREADS)
            Ws4[i] = Wg4[i];
    }

    // bias slice in registers
    float4 bia0 = reinterpret_cast<const float4*>(bias + dbase)[0];
    float4 bia1 = reinterpret_cast<const float4*>(bias + dbase)[1];

    const float4* Wsm4 = reinterpret_cast<const float4*>(Wsm);
    const int dq = lane * 2;        // float4 index of this lane within a W row (64 float4/row)

    for (int g = 0; g < G_PER_CTA; ++g) {
        const int b = blockIdx.x * G_PER_CTA + g;

        __syncthreads();                    // prev graph's compute done (ent/counts reuse)
        if (tid < NUM_N) counts[tid] = 0;
        __syncthreads();

        // ---- scatter: 1 thread = 1 edge ----
        if (tid < NUM_E) {
            const int e = tid;
            const int2 ei = reinterpret_cast<const int2*>(edge_index)[(long long)b * NUM_E + e];
            const unsigned int wb =
                __float_as_uint(edge_weight[(long long)b * NUM_E + e]);
            const int i1 = ei.x, i2 = ei.y;
            // phase 1: out[i1][i2] = w   (priority = e)
            int p1 = atomicAdd(&counts[i1], 1);
            if (p1 < CAP)
                ent[i1 * CAP + p1] =
                    ((unsigned long long)e << 40) |
                    ((unsigned long long)(unsigned)i2 << 32) | wb;
            // phase 2: out[i2][i1] = w   (priority = 256 + e, beats all of phase 1)
            int p2 = atomicAdd(&counts[i2], 1);
            if (p2 < CAP)
                ent[i2 * CAP + p2] =
                    ((unsigned long long)(256 + e) << 40) |
                    ((unsigned long long)(unsigned)i1 << 32) | wb;
        }
        __syncthreads();

        // ---- dedupe: zero weights of entries beaten by a higher-priority write
        //      to the same (row, col) ----
        for (int s = tid; s < NUM_N * CAP; s += THREADS) {
            const int r = s / CAP, j = s - r * CAP;
            const int c = min(counts[r], CAP);
            if (j < c) {
                const unsigned long long ej = ent[s];
                const unsigned int keyj = (unsigned int)(ej >> 32); // prio<<8 | col
                const unsigned int colj = keyj & 0xFFu;
                bool dead = false;
                for (int k = 0; k < c; ++k) {
                    const unsigned int keyk = (unsigned int)(ent[r * CAP + k] >> 32);
                    if ((keyk & 0xFFu) == colj && keyk > keyj) dead = true;
                }
                if (dead) ent[s] = ej & ~0xFFFFFFFFull;  // weight := 0.0f
            }
        }
        __syncthreads();

        // ---- compute & store: warp per row, rows stride WARPS ----
        const int*  nfb  = node_feat + (long long)b * NUM_N;
        float*      outb = out + (long long)b * NUM_N * D_DIM;
        for (int r = wrp; r < NUM_N; r += WARPS) {
            const int nf = nfb[r];                          // broadcast (L1 cached)
            const int c  = min(counts[r], CAP);

            // warp-cooperative entry fetch: lane j holds entry j (c <= 24 < 32)
            unsigned long long my = 0;
            if (lane < c) my = ent[r * CAP + lane];
            const float myw   = __uint_as_float((unsigned int)my);
            const int   mycol = (int)((my >> 32) & 0xFFu);

            const float4* Won = Wsm4 + (NUM_N + nf) * (D_DIM/4) + dq;
            float4 w0 = Won[0], w1 = Won[1];
            float4 a0, a1;
            a0.x = bia0.x + w0.x; a0.y = bia0.y + w0.y;
            a0.z = bia0.z + w0.z; a0.w = bia0.w + w0.w;
            a1.x = bia1.x + w1.x; a1.y = bia1.y + w1.y;
            a1.z = bia1.z + w1.z; a1.w = bia1.w + w1.w;

            for (int j = 0; j < c; ++j) {
                const float w   = __shfl_sync(0xFFFFFFFFu, myw,   j);
                const int   col = __shfl_sync(0xFFFFFFFFu, mycol, j);
                const float4* Wr = Wsm4 + col * (D_DIM/4) + dq;
                const float4 r0 = Wr[0], r1 = Wr[1];
                a0.x = fmaf(w, r0.x, a0.x); a0.y = fmaf(w, r0.y, a0.y);
                a0.z = fmaf(w, r0.z, a0.z); a0.w = fmaf(w, r0.w, a0.w);
                a1.x = fmaf(w, r1.x, a1.x); a1.y = fmaf(w, r1.y, a1.y);
                a1.z = fmaf(w, r1.z, a1.z); a1.w = fmaf(w, r1.w, a1.w);
            }

            float4* o4 = reinterpret_cast<float4*>(outb + r * D_DIM + dbase);
            o4[0] = a0;
            o4[1] = a1;
        }
    }
}

extern "C" void kernel_launch(void* const* d_in, const int* in_sizes, int n_in,
                              void* d_out, int out_size)
{
    const int*   edge_index  = (const int*)  d_in[0];
    const float* edge_weight = (const float*)d_in[1];
    const int*   node_feat   = (const int*)  d_in[2];
    const float* W           = (const float*)d_in[3];
    const float* bias        = (const float*)d_in[4];
    float*       out         = (float*)      d_out;

    cudaFuncSetAttribute(graph_embed_kernel,
                         cudaFuncAttributeMaxDynamicSharedMemorySize, SMEM_BYTES);
    graph_embed_kernel<<<NUM_B / G_PER_CTA, THREADS, SMEM_BYTES>>>(
        edge_index, edge_weight, node_feat, W, bias, out);
}

// round 5
// speedup vs baseline: 1.7664x; 1.4282x over previous
#include <cuda_runtime.h>
#include <cuda_fp16.h>

// GraphEmbedder: out[b,n,:] = pre[b,n,:] @ W + bias
// R3 re-bench (prior attempt hit broker timeout, never executed):
// W cached in SMEM as fp16 (halves L1 gather bytes: the 69.8%-busy L1 was the
// R2 limiter), accumulation via HFMA2 in half2 (4 instr/entry vs 8 FFMA),
// fp32 bias added at the single per-row conversion. Shfl prefetch pipelines the
// entry distribution. Error budget ~3-5e-4 aggregate vs 1e-3 tolerance.

#define NUM_B   4096
#define NUM_E   256
#define NUM_N   128
#define NUM_F   64
#define PRE_DIM 192        // N + F
#define D_DIM   256
#define CAP     24
#define G_PER_CTA 4
#define THREADS 768
#define WARPS   (THREADS/32)

// SMEM: W fp16 98304 B + ent 24576 B + counts 512 B = 123392 B
#define W_HALVES (PRE_DIM * D_DIM)
#define SMEM_BYTES (W_HALVES*2 + NUM_N*CAP*8 + NUM_N*4)

__global__ void __launch_bounds__(THREADS, 1)
graph_embed_kernel(const int*   __restrict__ edge_index,   // [B,E,2] int32
                   const float* __restrict__ edge_weight,  // [B,E]   f32
                   const int*   __restrict__ node_feat,    // [B,N]   int32
                   const float* __restrict__ Wg,           // [PRE,D] f32
                   const float* __restrict__ bias,         // [D]     f32
                   float*       __restrict__ out)          // [B,N,D] f32
{
    extern __shared__ unsigned char smem_raw[];
    __half* Wsm = reinterpret_cast<__half*>(smem_raw);
    unsigned long long* ent =
        reinterpret_cast<unsigned long long*>(smem_raw + W_HALVES * 2);
    int* counts = reinterpret_cast<int*>(ent + NUM_N * CAP);

    const int tid  = threadIdx.x;
    const int lane = tid & 31;
    const int wrp  = tid >> 5;
    const int dbase = lane * 8;     // each lane owns 8 consecutive d of 256

    // ---- convert W fp32 -> fp16 into SMEM (coalesced float2 -> half2) ----
    {
        const float2* Wg2 = reinterpret_cast<const float2*>(Wg);
        __half2* Ws2 = reinterpret_cast<__half2*>(Wsm);
        #pragma unroll 4
        for (int i = tid; i < W_HALVES / 2; i += THREADS) {
            float2 v = Wg2[i];
            Ws2[i] = __floats2half2_rn(v.x, v.y);
        }
    }

    // fp32 bias slice in registers
    float4 bia0 = reinterpret_cast<const float4*>(bias + dbase)[0];
    float4 bia1 = reinterpret_cast<const float4*>(bias + dbase)[1];

    for (int g = 0; g < G_PER_CTA; ++g) {
        const int b = blockIdx.x * G_PER_CTA + g;

        __syncthreads();                    // prev phase done (covers W fill at g=0)
        if (tid < NUM_N) counts[tid] = 0;
        __syncthreads();

        // ---- scatter: 1 thread = 1 edge ----
        if (tid < NUM_E) {
            const int e = tid;
            const int2 ei = reinterpret_cast<const int2*>(edge_index)[(long long)b * NUM_E + e];
            const unsigned int wb =
                __float_as_uint(edge_weight[(long long)b * NUM_E + e]);
            const int i1 = ei.x, i2 = ei.y;
            int p1 = atomicAdd(&counts[i1], 1);          // priority = e
            if (p1 < CAP)
                ent[i1 * CAP + p1] =
                    ((unsigned long long)e << 40) |
                    ((unsigned long long)(unsigned)i2 << 32) | wb;
            int p2 = atomicAdd(&counts[i2], 1);          // priority = 256 + e
            if (p2 < CAP)
                ent[i2 * CAP + p2] =
                    ((unsigned long long)(256 + e) << 40) |
                    ((unsigned long long)(unsigned)i1 << 32) | wb;
        }
        __syncthreads();

        // ---- dedupe: zero weights beaten by a higher-priority same-(row,col) write ----
        for (int s = tid; s < NUM_N * CAP; s += THREADS) {
            const int r = s / CAP, j = s - r * CAP;
            const int c = min(counts[r], CAP);
            if (j < c) {
                const unsigned long long ej = ent[s];
                const unsigned int keyj = (unsigned int)(ej >> 32); // prio<<8 | col
                const unsigned int colj = keyj & 0xFFu;
                bool dead = false;
                for (int k = 0; k < c; ++k) {
                    const unsigned int keyk = (unsigned int)(ent[r * CAP + k] >> 32);
                    if ((keyk & 0xFFu) == colj && keyk > keyj) dead = true;
                }
                if (dead) ent[s] = ej & ~0xFFFFFFFFull;  // weight := 0.0f
            }
        }
        __syncthreads();

        // ---- compute & store: warp per row ----
        const int*  nfb  = node_feat + (long long)b * NUM_N;
        float*      outb = out + (long long)b * NUM_N * D_DIM;
        for (int r = wrp; r < NUM_N; r += WARPS) {
            const int nf = nfb[r];
            const int c  = min(counts[r], CAP);

            // warp-cooperative entry fetch: lane j holds entry j (c <= 24)
            unsigned long long my = 0;
            if (lane < c) my = ent[r * CAP + lane];
            const float myw   = __uint_as_float((unsigned int)my);
            const int   mycol = (int)((my >> 32) & 0xFFu);

            // init accumulator with the one-hot W row (coefficient exactly 1.0)
            uint4 oh = *reinterpret_cast<const uint4*>(
                reinterpret_cast<const unsigned char*>(Wsm)
                + (NUM_N + nf) * (D_DIM * 2) + lane * 16);
            __half2 a0 = *reinterpret_cast<__half2*>(&oh.x);
            __half2 a1 = *reinterpret_cast<__half2*>(&oh.y);
            __half2 a2 = *reinterpret_cast<__half2*>(&oh.z);
            __half2 a3 = *reinterpret_cast<__half2*>(&oh.w);

            // software-pipelined entry loop (shfl latency overlapped with LDS+HFMA2)
            float wj = __shfl_sync(0xFFFFFFFFu, myw,   0);
            int   cj = __shfl_sync(0xFFFFFFFFu, mycol, 0);
            for (int j = 0; j < c; ++j) {
                const float wn = __shfl_sync(0xFFFFFFFFu, myw,   j + 1);
                const int   cn = __shfl_sync(0xFFFFFFFFu, mycol, j + 1);
                uint4 rw = *reinterpret_cast<const uint4*>(
                    reinterpret_cast<const unsigned char*>(Wsm)
                    + cj * (D_DIM * 2) + lane * 16);
                const __half2 wh = __float2half2_rn(wj);
                a0 = __hfma2(wh, *reinterpret_cast<__half2*>(&rw.x), a0);
                a1 = __hfma2(wh, *reinterpret_cast<__half2*>(&rw.y), a1);
                a2 = __hfma2(wh, *reinterpret_cast<__half2*>(&rw.z), a2);
                a3 = __hfma2(wh, *reinterpret_cast<__half2*>(&rw.w), a3);
                wj = wn; cj = cn;
            }

            // one fp32 conversion per row + fp32 bias
            const float2 f0 = __half22float2(a0);
            const float2 f1 = __half22float2(a1);
            const float2 f2 = __half22float2(a2);
            const float2 f3 = __half22float2(a3);
            float4 o0, o1;
            o0.x = bia0.x + f0.x; o0.y = bia0.y + f0.y;
            o0.z = bia0.z + f1.x; o0.w = bia0.w + f1.y;
            o1.x = bia1.x + f2.x; o1.y = bia1.y + f2.y;
            o1.z = bia1.z + f3.x; o1.w = bia1.w + f3.y;

            float4* o4 = reinterpret_cast<float4*>(outb + r * D_DIM + dbase);
            o4[0] = o0;
            o4[1] = o1;
        }
    }
}

extern "C" void kernel_launch(void* const* d_in, const int* in_sizes, int n_in,
                              void* d_out, int out_size)
{
    const int*   edge_index  = (const int*)  d_in[0];
    const float* edge_weight = (const float*)d_in[1];
    const int*   node_feat   = (const int*)  d_in[2];
    const float* W           = (const float*)d_in[3];
    const float* bias        = (const float*)d_in[4];
    float*       out         = (float*)      d_out;

    cudaFuncSetAttribute(graph_embed_kernel,
                         cudaFuncAttributeMaxDynamicSharedMemorySize, SMEM_BYTES);
    graph_embed_kernel<<<NUM_B / G_PER_CTA, THREADS, SMEM_BYTES>>>(
        edge_index, edge_weight, node_feat, W, bias, out);
}